// round 2
// baseline (speedup 1.0000x reference)
#include <cuda_runtime.h>

#define NROWS 16384
#define DIM   1024
#define NCENT 1024

#define BM 64
#define BN 64
#define BK 16
#define TM 4
#define TN 4

// Scratch (no allocations allowed)
__device__ float g_xsq[NROWS];
__device__ float g_csq[NCENT];
__device__ int   g_idx[NROWS];

// ---------------------------------------------------------------------------
// Row sum-of-squares: one block per row, 256 threads, deterministic tree.
// ---------------------------------------------------------------------------
__global__ __launch_bounds__(256) void xsq_kernel(const float* __restrict__ x) {
    __shared__ float s[256];
    const float* row = x + (size_t)blockIdx.x * DIM;
    float acc = 0.f;
    #pragma unroll
    for (int i = 0; i < DIM / 256; i++) {
        float v = row[threadIdx.x + i * 256];
        acc = fmaf(v, v, acc);
    }
    s[threadIdx.x] = acc;
    __syncthreads();
    #pragma unroll
    for (int off = 128; off > 0; off >>= 1) {
        if (threadIdx.x < off) s[threadIdx.x] += s[threadIdx.x + off];
        __syncthreads();
    }
    if (threadIdx.x == 0) g_xsq[blockIdx.x] = s[0];
}

__global__ __launch_bounds__(256) void csq_kernel(const float* __restrict__ c) {
    __shared__ float s[256];
    const float* row = c + (size_t)blockIdx.x * DIM;
    float acc = 0.f;
    #pragma unroll
    for (int i = 0; i < DIM / 256; i++) {
        float v = row[threadIdx.x + i * 256];
        acc = fmaf(v, v, acc);
    }
    s[threadIdx.x] = acc;
    __syncthreads();
    #pragma unroll
    for (int off = 128; off > 0; off >>= 1) {
        if (threadIdx.x < off) s[threadIdx.x] += s[threadIdx.x + off];
        __syncthreads();
    }
    if (threadIdx.x == 0) g_csq[blockIdx.x] = s[0];
}

// ---------------------------------------------------------------------------
// GEMM (x @ cT) with fused argmin epilogue.
// Grid: NROWS/BM = 256 blocks, 256 threads (16x16), 4x4 micro-tiles.
// d2 = (x_sq - 2*dot) + c_sq with rounding order matching the reference.
// ---------------------------------------------------------------------------
__global__ __launch_bounds__(256) void argmin_kernel(
    const float* __restrict__ x, const float* __restrict__ cent)
{
    __shared__ float As[BK][BM];
    __shared__ float Bs[BK][BN];
    __shared__ float sBest[BM][17];
    __shared__ int   sBidx[BM][17];

    const int tid = threadIdx.x;
    const int tx  = tid & 15;   // column group: cols tx*4 .. tx*4+3
    const int ty  = tid >> 4;   // row group:    rows ty*4 .. ty*4+3
    const int m0  = blockIdx.x * BM;

    float best[TM];
    int   bidx[TM];
    #pragma unroll
    for (int i = 0; i < TM; i++) { best[i] = 3.4e38f; bidx[i] = 0; }

    float xsq[TM];
    #pragma unroll
    for (int i = 0; i < TM; i++) xsq[i] = g_xsq[m0 + ty * TM + i];

    // loaders: thread -> (row tid/4, k-offset (tid%4)*4), float4 along k
    const int lr = tid >> 2;
    const int lk = (tid & 3) * 4;

    for (int n0 = 0; n0 < NCENT; n0 += BN) {
        float acc[TM][TN];
        #pragma unroll
        for (int i = 0; i < TM; i++)
            #pragma unroll
            for (int j = 0; j < TN; j++) acc[i][j] = 0.f;

        for (int k0 = 0; k0 < DIM; k0 += BK) {
            float4 va = *(const float4*)(x    + (size_t)(m0 + lr) * DIM + k0 + lk);
            float4 vb = *(const float4*)(cent + (size_t)(n0 + lr) * DIM + k0 + lk);
            As[lk + 0][lr] = va.x; As[lk + 1][lr] = va.y;
            As[lk + 2][lr] = va.z; As[lk + 3][lr] = va.w;
            Bs[lk + 0][lr] = vb.x; Bs[lk + 1][lr] = vb.y;
            Bs[lk + 2][lr] = vb.z; Bs[lk + 3][lr] = vb.w;
            __syncthreads();

            #pragma unroll
            for (int kk = 0; kk < BK; kk++) {
                float4 a4 = *(const float4*)&As[kk][ty * TM];
                float4 b4 = *(const float4*)&Bs[kk][tx * TN];
                float a[TM] = {a4.x, a4.y, a4.z, a4.w};
                float b[TN] = {b4.x, b4.y, b4.z, b4.w};
                #pragma unroll
                for (int i = 0; i < TM; i++)
                    #pragma unroll
                    for (int j = 0; j < TN; j++)
                        acc[i][j] = fmaf(a[i], b[j], acc[i][j]);
            }
            __syncthreads();
        }

        // epilogue: d2 = (x_sq - 2*dot) + c_sq ; track running first-min
        #pragma unroll
        for (int j = 0; j < TN; j++) {
            const int c = n0 + tx * TN + j;
            const float cs = g_csq[c];
            #pragma unroll
            for (int i = 0; i < TM; i++) {
                float d = fmaf(-2.0f, acc[i][j], xsq[i]) + cs;
                if (d < best[i]) { best[i] = d; bidx[i] = c; }
            }
        }
    }

    // cross-thread reduction per row (tie-break toward smallest index)
    #pragma unroll
    for (int i = 0; i < TM; i++) {
        sBest[ty * TM + i][tx] = best[i];
        sBidx[ty * TM + i][tx] = bidx[i];
    }
    __syncthreads();
    if (tid < BM) {
        float b = sBest[tid][0];
        int  bi = sBidx[tid][0];
        #pragma unroll
        for (int t = 1; t < 16; t++) {
            float v = sBest[tid][t];
            int  vi = sBidx[tid][t];
            if (v < b || (v == b && vi < bi)) { b = v; bi = vi; }
        }
        g_idx[m0 + tid] = bi;
    }
}

// ---------------------------------------------------------------------------
// Gather: out[r] = table[idx[r]] + bias. One block per row; table (4MB) is
// fully L2-resident, so this is output-write bound.
// ---------------------------------------------------------------------------
__global__ __launch_bounds__(256) void gather_kernel(
    const float* __restrict__ table, const float* __restrict__ bias,
    float* __restrict__ out)
{
    const int r = blockIdx.x;
    const int idx = g_idx[r];
    const float4* src = (const float4*)(table + (size_t)idx * DIM);
    const float4* bv  = (const float4*)bias;
    float4* dst = (float4*)(out + (size_t)r * DIM);
    float4 a = src[threadIdx.x];
    float4 b = bv[threadIdx.x];
    dst[threadIdx.x] = make_float4(a.x + b.x, a.y + b.y, a.z + b.z, a.w + b.w);
}

// ---------------------------------------------------------------------------
extern "C" void kernel_launch(void* const* d_in, const int* in_sizes, int n_in,
                              void* d_out, int out_size) {
    const float* x     = (const float*)d_in[0];  // [4,4096,1024]
    const float* cent  = (const float*)d_in[1];  // [1024,1024]
    const float* table = (const float*)d_in[2];  // [1024,1024]
    const float* bias  = (const float*)d_in[3];  // [1024]
    float* out = (float*)d_out;

    xsq_kernel<<<NROWS, 256>>>(x);
    csq_kernel<<<NCENT, 256>>>(cent);
    argmin_kernel<<<NROWS / BM, 256>>>(x, cent);
    gather_kernel<<<NROWS, 256>>>(table, bias, out);
}

// round 3
// speedup vs baseline: 6.0372x; 6.0372x over previous
#include <cuda_runtime.h>
#include <cuda_bf16.h>
#include <cstdint>

#define NROWS 16384
#define DIM   1024
#define NCENT 1024
#define MARGIN 0.35f

#define BM 128
#define BN 128
#define BK 32
#define PAD_K 40   // bf16 elems per smem row (80B stride -> conflict-free ldmatrix)

// ---- scratch (device globals only; no runtime allocation allowed) ----
__device__ float         g_xsq[NROWS];
__device__ float         g_csq[NCENT];
__device__ unsigned      g_rowmin[NROWS];
__device__ int           g_idx[NROWS];
__device__ __nv_bfloat16 g_xb[(size_t)NROWS * DIM];      // 32 MB
__device__ __nv_bfloat16 g_cb[(size_t)NCENT * DIM];      //  2 MB
__device__ float         g_scores[(size_t)NROWS * NCENT];// 64 MB

// ---------------------------------------------------------------------------
// Fused: row sum-of-squares (exact fp32) + bf16 conversion + rowmin init.
// ---------------------------------------------------------------------------
__global__ __launch_bounds__(256) void prep_x_kernel(const float* __restrict__ x) {
    __shared__ float s[256];
    const int r = blockIdx.x, t = threadIdx.x;
    const float4 v = ((const float4*)(x + (size_t)r * DIM))[t];
    // bf16 conversion
    __nv_bfloat162 b01, b23;
    b01.x = __float2bfloat16(v.x); b01.y = __float2bfloat16(v.y);
    b23.x = __float2bfloat16(v.z); b23.y = __float2bfloat16(v.w);
    __nv_bfloat162* dst = (__nv_bfloat162*)(g_xb + (size_t)r * DIM);
    dst[t * 2 + 0] = b01;
    dst[t * 2 + 1] = b23;
    // sum of squares
    float acc = fmaf(v.x, v.x, 0.f);
    acc = fmaf(v.y, v.y, acc);
    acc = fmaf(v.z, v.z, acc);
    acc = fmaf(v.w, v.w, acc);
    s[t] = acc;
    __syncthreads();
    #pragma unroll
    for (int off = 128; off > 0; off >>= 1) {
        if (t < off) s[t] += s[t + off];
        __syncthreads();
    }
    if (t == 0) {
        g_xsq[r] = s[0];
        g_rowmin[r] = 0x7F7FFFFFu;  // FLT_MAX bits
    }
}

__global__ __launch_bounds__(256) void prep_c_kernel(const float* __restrict__ c) {
    __shared__ float s[256];
    const int r = blockIdx.x, t = threadIdx.x;
    const float4 v = ((const float4*)(c + (size_t)r * DIM))[t];
    __nv_bfloat162 b01, b23;
    b01.x = __float2bfloat16(v.x); b01.y = __float2bfloat16(v.y);
    b23.x = __float2bfloat16(v.z); b23.y = __float2bfloat16(v.w);
    __nv_bfloat162* dst = (__nv_bfloat162*)(g_cb + (size_t)r * DIM);
    dst[t * 2 + 0] = b01;
    dst[t * 2 + 1] = b23;
    float acc = fmaf(v.x, v.x, 0.f);
    acc = fmaf(v.y, v.y, acc);
    acc = fmaf(v.z, v.z, acc);
    acc = fmaf(v.w, v.w, acc);
    s[t] = acc;
    __syncthreads();
    #pragma unroll
    for (int off = 128; off > 0; off >>= 1) {
        if (t < off) s[t] += s[t + off];
        __syncthreads();
    }
    if (t == 0) g_csq[r] = s[0];
}

// ---------------------------------------------------------------------------
// Stage 1: bf16 tensor-core GEMM producing approximate d2 scores + row mins.
// Block tile 128x128x32, 8 warps (4M x 2N), warp tile 32x64, m16n8k16 MMA.
// ---------------------------------------------------------------------------
__device__ __forceinline__ void cp16(uint32_t dst, const void* src) {
    asm volatile("cp.async.cg.shared.global [%0], [%1], 16;\n" :: "r"(dst), "l"(src));
}
__device__ __forceinline__ void ldsm4(uint32_t* r, uint32_t addr) {
    asm volatile("ldmatrix.sync.aligned.m8n8.x4.shared.b16 {%0,%1,%2,%3}, [%4];"
                 : "=r"(r[0]), "=r"(r[1]), "=r"(r[2]), "=r"(r[3]) : "r"(addr));
}
__device__ __forceinline__ void mma16816(float* c, const uint32_t* a, uint32_t b0, uint32_t b1) {
    asm volatile("mma.sync.aligned.m16n8k16.row.col.f32.bf16.bf16.f32 "
                 "{%0,%1,%2,%3}, {%4,%5,%6,%7}, {%8,%9}, {%0,%1,%2,%3};"
                 : "+f"(c[0]), "+f"(c[1]), "+f"(c[2]), "+f"(c[3])
                 : "r"(a[0]), "r"(a[1]), "r"(a[2]), "r"(a[3]), "r"(b0), "r"(b1));
}

__global__ __launch_bounds__(256, 2) void mma_score_kernel() {
    __shared__ __align__(128) __nv_bfloat16 As[2][BM * PAD_K];
    __shared__ __align__(128) __nv_bfloat16 Bs[2][BN * PAD_K];

    const int tid  = threadIdx.x;
    const int warp = tid >> 5, lane = tid & 31;
    const int wm = warp >> 1, wn = warp & 1;
    const int m0 = blockIdx.y * BM;
    const int n0 = blockIdx.x * BN;

    float acc[2][8][4];
    #pragma unroll
    for (int i = 0; i < 2; i++)
        #pragma unroll
        for (int j = 0; j < 8; j++)
            #pragma unroll
            for (int k = 0; k < 4; k++) acc[i][j][k] = 0.f;

    uint32_t sA[2], sB[2];
    sA[0] = (uint32_t)__cvta_generic_to_shared(&As[0][0]);
    sA[1] = (uint32_t)__cvta_generic_to_shared(&As[1][0]);
    sB[0] = (uint32_t)__cvta_generic_to_shared(&Bs[0][0]);
    sB[1] = (uint32_t)__cvta_generic_to_shared(&Bs[1][0]);

    // tile loaders: thread -> row tid>>1, 32B half (tid&1)
    const int lr = tid >> 1;
    const int lc = (tid & 1) * 16;
    const uint32_t dOffA = (uint32_t)(lr * PAD_K + lc) * 2;

    auto load_tile = [&](int buf, int k0) {
        const __nv_bfloat16* srcA = g_xb + (size_t)(m0 + lr) * DIM + k0 + lc;
        cp16(sA[buf] + dOffA,      srcA);
        cp16(sA[buf] + dOffA + 16, srcA + 8);
        const __nv_bfloat16* srcB = g_cb + (size_t)(n0 + lr) * DIM + k0 + lc;
        cp16(sB[buf] + dOffA,      srcB);
        cp16(sB[buf] + dOffA + 16, srcB + 8);
    };

    load_tile(0, 0);
    asm volatile("cp.async.commit_group;");
    asm volatile("cp.async.wait_group 0;");
    __syncthreads();

    // precomputed ldmatrix lane geometry
    const int a_row = (lane & 7) + ((lane >> 3) & 1) * 8;   // within 16-row frag
    const int a_kof = (lane >> 4) * 8;
    const int b_row = (lane & 7) + (lane >> 4) * 8;         // n within 16
    const int b_kof = ((lane >> 3) & 1) * 8;

    for (int kt = 0; kt < DIM / BK; kt++) {
        const int buf = kt & 1;
        if (kt + 1 < DIM / BK) {
            load_tile(buf ^ 1, (kt + 1) * BK);
            asm volatile("cp.async.commit_group;");
        }

        #pragma unroll
        for (int ks = 0; ks < BK; ks += 16) {
            uint32_t af[2][4];
            #pragma unroll
            for (int mi = 0; mi < 2; mi++) {
                uint32_t addr = sA[buf] +
                    (uint32_t)((wm * 32 + mi * 16 + a_row) * PAD_K + ks + a_kof) * 2;
                ldsm4(af[mi], addr);
            }
            #pragma unroll
            for (int nt = 0; nt < 4; nt++) {
                uint32_t bf[4];
                uint32_t addr = sB[buf] +
                    (uint32_t)((wn * 64 + nt * 16 + b_row) * PAD_K + ks + b_kof) * 2;
                ldsm4(bf, addr);
                #pragma unroll
                for (int mi = 0; mi < 2; mi++) {
                    mma16816(acc[mi][2 * nt + 0], af[mi], bf[0], bf[1]);
                    mma16816(acc[mi][2 * nt + 1], af[mi], bf[2], bf[3]);
                }
            }
        }

        asm volatile("cp.async.wait_group 0;");
        __syncthreads();
    }

    // epilogue: d2 = fmaf(-2, dot, xsq) + csq ; write scores + per-row min
    #pragma unroll
    for (int mi = 0; mi < 2; mi++) {
        #pragma unroll
        for (int h = 0; h < 2; h++) {
            const int gr = m0 + wm * 32 + mi * 16 + h * 8 + (lane >> 2);
            const float xs = g_xsq[gr];
            float lmin = 3.4e38f;
            float* srow = g_scores + (size_t)gr * NCENT;
            #pragma unroll
            for (int ni = 0; ni < 8; ni++) {
                const int gc = n0 + wn * 64 + ni * 8 + (lane & 3) * 2;
                const float v0 = fmaf(-2.f, acc[mi][ni][h * 2 + 0], xs) + g_csq[gc];
                const float v1 = fmaf(-2.f, acc[mi][ni][h * 2 + 1], xs) + g_csq[gc + 1];
                *(float2*)(srow + gc) = make_float2(v0, v1);
                lmin = fminf(lmin, fminf(v0, v1));
            }
            lmin = fminf(lmin, __shfl_xor_sync(0xffffffffu, lmin, 1));
            lmin = fminf(lmin, __shfl_xor_sync(0xffffffffu, lmin, 2));
            if ((lane & 3) == 0)
                atomicMin(&g_rowmin[gr], __float_as_uint(lmin));  // d2 > 0 always
        }
    }
}

// ---------------------------------------------------------------------------
// Stage 2: exact fp32 rescore of candidates within margin of approx min.
// One block per row. Candidate set provably contains the true argmin.
// ---------------------------------------------------------------------------
__global__ __launch_bounds__(256) void rescore_kernel(
    const float* __restrict__ x, const float* __restrict__ cent)
{
    __shared__ int   s_cand[NCENT];
    __shared__ int   s_cnt;
    __shared__ float s_red[8];

    const int r = blockIdx.x, t = threadIdx.x;
    if (t == 0) s_cnt = 0;
    __syncthreads();

    const float thr = __uint_as_float(g_rowmin[r]) + MARGIN;
    const float* srow = g_scores + (size_t)r * NCENT;
    #pragma unroll
    for (int j = t; j < NCENT; j += 256) {
        if (srow[j] <= thr) {
            int p = atomicAdd(&s_cnt, 1);
            s_cand[p] = j;
        }
    }
    __syncthreads();
    const int cnt = s_cnt;

    const float* xr = x + (size_t)r * DIM;
    const float x0 = xr[t], x1 = xr[t + 256], x2 = xr[t + 512], x3 = xr[t + 768];
    const float xs = g_xsq[r];

    float best = 3.4e38f;
    int bidx = NCENT;
    for (int ci = 0; ci < cnt; ci++) {
        const int c = s_cand[ci];
        const float* cr = cent + (size_t)c * DIM;
        float a = fmaf(x0, cr[t], 0.f);
        a = fmaf(x1, cr[t + 256], a);
        a = fmaf(x2, cr[t + 512], a);
        a = fmaf(x3, cr[t + 768], a);
        #pragma unroll
        for (int o = 16; o > 0; o >>= 1)
            a += __shfl_xor_sync(0xffffffffu, a, o);
        if ((t & 31) == 0) s_red[t >> 5] = a;
        __syncthreads();
        if (t == 0) {
            float dot = s_red[0];
            #pragma unroll
            for (int w = 1; w < 8; w++) dot += s_red[w];
            const float d = fmaf(-2.f, dot, xs) + g_csq[c];
            if (d < best || (d == best && c < bidx)) { best = d; bidx = c; }
        }
        __syncthreads();
    }
    if (t == 0) g_idx[r] = bidx;
}

// ---------------------------------------------------------------------------
// Gather: out[r] = table[idx[r]] + bias (table is L2-resident; write-bound).
// ---------------------------------------------------------------------------
__global__ __launch_bounds__(256) void gather_kernel(
    const float* __restrict__ table, const float* __restrict__ bias,
    float* __restrict__ out)
{
    const int r = blockIdx.x;
    const int idx = g_idx[r];
    const float4* src = (const float4*)(table + (size_t)idx * DIM);
    const float4* bv  = (const float4*)bias;
    float4* dst = (float4*)(out + (size_t)r * DIM);
    float4 a = src[threadIdx.x];
    float4 b = bv[threadIdx.x];
    dst[threadIdx.x] = make_float4(a.x + b.x, a.y + b.y, a.z + b.z, a.w + b.w);
}

// ---------------------------------------------------------------------------
extern "C" void kernel_launch(void* const* d_in, const int* in_sizes, int n_in,
                              void* d_out, int out_size) {
    const float* x     = (const float*)d_in[0];  // [4,4096,1024]
    const float* cent  = (const float*)d_in[1];  // [1024,1024]
    const float* table = (const float*)d_in[2];  // [1024,1024]
    const float* bias  = (const float*)d_in[3];  // [1024]
    float* out = (float*)d_out;

    prep_x_kernel<<<NROWS, 256>>>(x);
    prep_c_kernel<<<NCENT, 256>>>(cent);
    mma_score_kernel<<<dim3(NCENT / BN, NROWS / BM), 256>>>();
    rescore_kernel<<<NROWS, 256>>>(x, cent);
    gather_kernel<<<NROWS, 256>>>(table, bias, out);
}